// round 15
// baseline (speedup 1.0000x reference)
#include <cuda_runtime.h>
#include <math.h>

// Problem constants
#define Bsz   32
#define Tn    512
#define Jn    25
#define DENC  256
#define Hn    512
#define G4    2048      // 4*H
#define NB    128       // persistent recurrence grid (co-resident)
#define NB2   64        // blocks per direction

// ---------------- scratch (device globals; no allocations) ----------------
__device__ float    g_enc [Bsz * Tn * DENC];
__device__ float    g_xg  [2L * Tn * Bsz * G4];           // [d][t][b][4H]
__device__ float    g_out0[Bsz * Tn * 2 * Hn];            // [b][t][2H]
__device__ float    g_out1[Bsz * Tn * 2 * Hn];
__device__ __align__(16) unsigned g_h[2][2 * Bsz * Hn];   // tf32 bits, double-buffered
__device__ unsigned g_flag[2][NB2 * 32];                  // per-block flags, 128B apart

// ---------------- helpers --------------------------------------------------
__device__ __forceinline__ unsigned f2tf(float x) {
    unsigned u;
    asm("cvt.rna.tf32.f32 %0, %1;" : "=r"(u) : "f"(x));
    return u;
}

__device__ __forceinline__ void mma_tf32(float* c,
                                         unsigned a0, unsigned a1,
                                         unsigned a2, unsigned a3,
                                         unsigned b0, unsigned b1) {
    asm("mma.sync.aligned.m16n8k8.row.col.f32.tf32.tf32.f32 "
        "{%0,%1,%2,%3}, {%4,%5,%6,%7}, {%8,%9}, {%0,%1,%2,%3};"
        : "+f"(c[0]), "+f"(c[1]), "+f"(c[2]), "+f"(c[3])
        : "r"(a0), "r"(a1), "r"(a2), "r"(a3), "r"(b0), "r"(b1));
}

__device__ __forceinline__ void st_release_gpu(unsigned* p, unsigned v) {
    asm volatile("st.release.gpu.global.u32 [%0], %1;" :: "l"(p), "r"(v) : "memory");
}
__device__ __forceinline__ unsigned ld_acquire_gpu(const unsigned* p) {
    unsigned v;
    asm volatile("ld.acquire.gpu.global.u32 %0, [%1];" : "=r"(v) : "l"(p) : "memory");
    return v;
}
__device__ __forceinline__ unsigned ldcg(const unsigned* p) {
    unsigned v;
    asm volatile("ld.global.cg.b32 %0, [%1];" : "=r"(v) : "l"(p) : "memory");
    return v;
}

// ---------------- zero the output buffers ---------------------------------
__global__ void zero_kernel() {
    const int n4 = (Bsz * Tn * 2 * Hn) / 4;
    float4 z = make_float4(0.f, 0.f, 0.f, 0.f);
    for (int i = blockIdx.x * blockDim.x + threadIdx.x; i < n4;
         i += gridDim.x * blockDim.x) {
        reinterpret_cast<float4*>(g_out0)[i] = z;
        reinterpret_cast<float4*>(g_out1)[i] = z;
    }
}

// ---------------- encoder: relu(masked_xy @ W^T + b) ----------------------
__global__ void enc_kernel(const float* __restrict__ feats,
                           const float* __restrict__ W,
                           const float* __restrict__ bias) {
    __shared__ float xs[2 * Jn];
    const int bt  = blockIdx.x;
    const int tid = threadIdx.x;
    const float* f = feats + (size_t)bt * (Jn * 3);
    if (tid < Jn) {
        float c = (f[tid * 3 + 2] > 0.1f) ? 1.f : 0.f;
        xs[tid * 2 + 0] = f[tid * 3 + 0] * c;
        xs[tid * 2 + 1] = f[tid * 3 + 1] * c;
    }
    __syncthreads();
    const float* w = W + tid * (2 * Jn);
    float s = bias[tid];
#pragma unroll
    for (int k = 0; k < 2 * Jn; ++k) s += xs[k] * w[k];
    g_enc[(size_t)bt * DENC + tid] = fmaxf(s, 0.f);
}

// ---------------- input projection GEMM (tf32, k-tile 32 ping-pong) -------
// out_xg[d][t][b][g] = A[m=b*T+t,:K] . W[d][g,:K] + bias[d][g]
// block 128x128, 8 warps (2m x 4n), k-tile 32, 1 sync per tile
#define PROJ_SMEM (4 * 128 * 36 * 4)
extern __shared__ unsigned smp[];

__global__ void __launch_bounds__(256)
proj_gemm(int srcSel, int K, const float* __restrict__ W,
          const float* __restrict__ bias) {
    const float* A  = srcSel ? g_out0 : g_enc;
    const int d  = blockIdx.z;
    const float* Wd = W + (size_t)d * G4 * K;
    const float* bd = bias + d * G4;
    const int n0 = blockIdx.x * 128;
    const int m0 = blockIdx.y * 128;

    unsigned* As = smp;                   // [2][128*36]
    unsigned* Bs = smp + 2 * 128 * 36;

    const int tid  = threadIdx.x;
    const int lane = tid & 31;
    const int wid  = tid >> 5;
    const int wm   = (wid >> 2) * 64;
    const int wn   = (wid & 3) * 32;

    float acc[4][4][4];
#pragma unroll
    for (int mt = 0; mt < 4; ++mt)
#pragma unroll
        for (int nt = 0; nt < 4; ++nt)
#pragma unroll
            for (int i = 0; i < 4; ++i) acc[mt][nt][i] = 0.f;

    float4 ra[4], rw[4];
#pragma unroll
    for (int j = 0; j < 4; ++j) {
        int u = tid + j * 256, r = u >> 3, kq = (u & 7) << 2;
        ra[j] = *reinterpret_cast<const float4*>(A  + (size_t)(m0 + r) * K + kq);
        rw[j] = *reinterpret_cast<const float4*>(Wd + (size_t)(n0 + r) * K + kq);
    }

    const int KT = K >> 5;
    for (int kt = 0; kt < KT; ++kt) {
        const int p = kt & 1;
#pragma unroll
        for (int j = 0; j < 4; ++j) {
            int u = tid + j * 256, r = u >> 3, kq = (u & 7) << 2;
            uint4 ua, uw;
            ua.x = f2tf(ra[j].x); ua.y = f2tf(ra[j].y);
            ua.z = f2tf(ra[j].z); ua.w = f2tf(ra[j].w);
            uw.x = f2tf(rw[j].x); uw.y = f2tf(rw[j].y);
            uw.z = f2tf(rw[j].z); uw.w = f2tf(rw[j].w);
            *reinterpret_cast<uint4*>(As + p * 4608 + r * 36 + kq) = ua;
            *reinterpret_cast<uint4*>(Bs + p * 4608 + r * 36 + kq) = uw;
        }
        __syncthreads();     // single barrier per k-tile (ping-pong)

        if (kt + 1 < KT) {   // prefetch next tile while computing
            int kb = (kt + 1) * 32;
#pragma unroll
            for (int j = 0; j < 4; ++j) {
                int u = tid + j * 256, r = u >> 3, kq = (u & 7) << 2;
                ra[j] = *reinterpret_cast<const float4*>(A  + (size_t)(m0 + r) * K + kb + kq);
                rw[j] = *reinterpret_cast<const float4*>(Wd + (size_t)(n0 + r) * K + kb + kq);
            }
        }

        const unsigned* Ab = As + p * 4608;
        const unsigned* Bb = Bs + p * 4608;
#pragma unroll
        for (int kk = 0; kk < 32; kk += 8) {
            unsigned af[4][4], bf[4][2];
#pragma unroll
            for (int mt = 0; mt < 4; ++mt) {
                const unsigned* pp = Ab + (wm + mt * 16 + (lane >> 2)) * 36 + kk + (lane & 3);
                af[mt][0] = pp[0];
                af[mt][1] = pp[8 * 36];
                af[mt][2] = pp[4];
                af[mt][3] = pp[8 * 36 + 4];
            }
#pragma unroll
            for (int nt = 0; nt < 4; ++nt) {
                const unsigned* pp = Bb + (wn + nt * 8 + (lane >> 2)) * 36 + kk + (lane & 3);
                bf[nt][0] = pp[0];
                bf[nt][1] = pp[4];
            }
#pragma unroll
            for (int mt = 0; mt < 4; ++mt)
#pragma unroll
                for (int nt = 0; nt < 4; ++nt)
                    mma_tf32(acc[mt][nt], af[mt][0], af[mt][1], af[mt][2], af[mt][3],
                             bf[nt][0], bf[nt][1]);
        }
        __syncthreads();
    }

    // epilogue: bias + scatter to g_xg
#pragma unroll
    for (int mt = 0; mt < 4; ++mt) {
        int mrow0 = m0 + wm + mt * 16 + (lane >> 2);
#pragma unroll
        for (int nt = 0; nt < 4; ++nt) {
            int n = n0 + wn + nt * 8 + (lane & 3) * 2;
            float bv0 = bd[n], bv1 = bd[n + 1];
#pragma unroll
            for (int h = 0; h < 2; ++h) {
                int m  = mrow0 + h * 8;
                int t  = m & (Tn - 1);
                int bb = m >> 9;
                float* cp = g_xg + (((size_t)d * Tn + t) * Bsz + bb) * G4 + n;
                *reinterpret_cast<float2*>(cp) =
                    make_float2(acc[mt][nt][h * 2 + 0] + bv0,
                                acc[mt][nt][h * 2 + 1] + bv1);
            }
        }
    }
}

// ---------------- persistent bidirectional LSTM recurrence (tf32 MMA) -----
// R13 + direct-from-L2 A fragments: after the producer-subset poll, h
// fragments are loaded straight from g_h with ld.global.cg (L1-bypassed,
// ordered by the flag acquire) into double-buffered register groups feeding
// the MMAs. No cp.async, no wait-all, no smem h buffer, no LDS on the chain.
// h writes remain behind the full-block partials barrier (which transitively
// requires all 64 producer flags), preserving the R13 parity-safety proof.
#define REC_SMEM (32 * 136 * 4)
extern __shared__ unsigned smr[];

__global__ void __launch_bounds__(256, 1)
rec_kernel(const float* __restrict__ whh,      // [2][4H][H]
           const int*   __restrict__ lengths,
           int outSel) {
    float* part = (float*)smr;                     // [32 b][136]
    float* out = outSel ? g_out1 : g_out0;
    const float* xg = g_xg;

    const int tid  = threadIdx.x;
    const int lane = tid & 31;
    const int wid  = tid >> 5;
    const int bx   = blockIdx.x;
    const int d    = bx >> 6;
    const int myblk = bx & 63;
    const int j0   = myblk << 3;
    const int mb   = wid & 1;             // batch half
    const int kc   = wid >> 1;            // K chunk (0..3), 128 k each

    // per-launch flag base + max length (uniform across all blocks)
    __shared__ unsigned s_base;
    __shared__ int s_maxlen;
    if (wid == 0) {
        int L = lengths[lane];
#pragma unroll
        for (int off = 16; off > 0; off >>= 1)
            L = max(L, __shfl_xor_sync(0xffffffffu, L, off));
        if (lane == 0) {
            s_maxlen = L;
            s_base = *(volatile unsigned*)&g_flag[d][myblk * 32];
        }
    }

    // stationary W fragments (B side): b0,b1 per (ks, nt=q)
    unsigned wb0[16][4], wb1[16][4];
    {
        const float* wdb = whh + (size_t)d * G4 * Hn;
#pragma unroll
        for (int ks = 0; ks < 16; ++ks)
#pragma unroll
            for (int nt = 0; nt < 4; ++nt) {
                const float* wp = wdb + (size_t)(nt * Hn + j0 + (lane >> 2)) * Hn
                                  + kc * 128 + ks * 8 + (lane & 3);
                wb0[ks][nt] = f2tf(wp[0]);
                wb1[ks][nt] = f2tf(wp[4]);
            }
    }

    // phase-2 identity: jj-major -> coalesced gmem
    const int jj = tid & 7;
    const int b2 = tid >> 3;              // 0..31
    const int len = lengths[b2];
    const int hidx = (d * Bsz + b2) * Hn + j0 + jj;
    float c_reg = 0.f;
    unsigned h_bits = 0u;
    g_h[0][hidx] = 0u;

    __syncthreads();
    const unsigned base = s_base;
    const int smax = s_maxlen;

    // announce h buffer 0 zeroed (consumers poll per-warp in the loop)
    if (tid == 0) st_release_gpu(&g_flag[d][myblk * 32], base + 1);

    // per-warp fragment base pointers (row = mb*16 + lane>>2)
    const int fragoff = (d * Bsz + mb * 16 + (lane >> 2)) * Hn
                        + kc * 128 + (lane & 3);
    const unsigned* hb0 = g_h[0] + fragoff;
    const unsigned* hb1 = g_h[1] + fragoff;
    // my 16 producer flags: blocks kc*16 .. kc*16+15 of my direction
    unsigned* prod_flag = (lane < 16)
        ? &g_flag[d][(kc * 16 + lane) * 32] : (unsigned*)0;

    for (int s = 0; s < smax; ++s) {
        const int pw_ = (s & 1) ^ 1;
        const bool act = s < len;
        const int t = d ? (len - 1 - s) : s;

        // prefetch xg (independent of h; 32B-coalesced per (b,q) group)
        float xv0 = 0.f, xv1 = 0.f, xv2 = 0.f, xv3 = 0.f;
        if (act) {
            const float* xr = xg + (((size_t)d * Tn + t) * Bsz + b2) * G4 + j0 + jj;
            xv0 = xr[0];
            xv1 = xr[Hn];
            xv2 = xr[2 * Hn];
            xv3 = xr[3 * Hn];
        }

        // wait for MY 16 producers only
        {
            const unsigned target = base + 1 + s;
            if (lane < 16) {
                while ((int)(ld_acquire_gpu(prod_flag) - target) < 0) { }
            }
            __syncwarp();
        }

        float acc[4][4];
#pragma unroll
        for (int nt = 0; nt < 4; ++nt)
#pragma unroll
            for (int i = 0; i < 4; ++i) acc[nt][i] = 0.f;

        // A fragments straight from L2 (cg), double-buffered groups of 4 ks
        {
            const unsigned* hb = (s & 1) ? hb1 : hb0;
            unsigned hA[2][4][4];
#pragma unroll
            for (int k4 = 0; k4 < 4; ++k4) {
                int off = k4 * 8;
                hA[0][k4][0] = ldcg(hb + off);
                hA[0][k4][2] = ldcg(hb + off + 4);
                hA[0][k4][1] = ldcg(hb + off + 8 * Hn);
                hA[0][k4][3] = ldcg(hb + off + 8 * Hn + 4);
            }
#pragma unroll
            for (int g = 0; g < 4; ++g) {
                const int cur = g & 1, nxt = cur ^ 1;
                if (g < 3) {
#pragma unroll
                    for (int k4 = 0; k4 < 4; ++k4) {
                        int off = (g + 1) * 32 + k4 * 8;
                        hA[nxt][k4][0] = ldcg(hb + off);
                        hA[nxt][k4][2] = ldcg(hb + off + 4);
                        hA[nxt][k4][1] = ldcg(hb + off + 8 * Hn);
                        hA[nxt][k4][3] = ldcg(hb + off + 8 * Hn + 4);
                    }
                }
#pragma unroll
                for (int k4 = 0; k4 < 4; ++k4) {
                    const int ks = g * 4 + k4;
#pragma unroll
                    for (int nt = 0; nt < 4; ++nt)
                        mma_tf32(acc[nt], hA[cur][k4][0], hA[cur][k4][1],
                                 hA[cur][k4][2], hA[cur][k4][3],
                                 wb0[ks][nt], wb1[ks][nt]);
                }
            }
        }

        // write K-chunk partials: part[batch][kc*32 + q*8 + jcol]
        {
            const int b_lo = mb * 16 + (lane >> 2);
            const int col  = kc * 32 + ((lane & 3) << 1);
#pragma unroll
            for (int nt = 0; nt < 4; ++nt) {
                float* pp = part + b_lo * 136 + col + nt * 8;
                *reinterpret_cast<float2*>(pp) =
                    make_float2(acc[nt][0], acc[nt][1]);
                *reinterpret_cast<float2*>(pp + 8 * 136) =
                    make_float2(acc[nt][2], acc[nt][3]);
            }
        }
        __syncthreads();                 // partials complete (all 64 polled)

        // phase 2: reduce 4 K-chunk partials + gates (conflict-free reads)
        float hn = 0.f;
        if (act) {
            const float* pb = part + b2 * 136 + jj;
            float gv[4];
#pragma unroll
            for (int q = 0; q < 4; ++q) {
                float v = (q == 0) ? xv0 : (q == 1) ? xv1 : (q == 2) ? xv2 : xv3;
#pragma unroll
                for (int k2 = 0; k2 < 4; ++k2)
                    v += pb[k2 * 32 + q * 8];
                gv[q] = v;
            }
            float ig = 1.f / (1.f + __expf(-gv[0]));
            float fg = 1.f / (1.f + __expf(-gv[1]));
            float gg = tanhf(gv[2]);
            float og = 1.f / (1.f + __expf(-gv[3]));
            c_reg = fg * c_reg + ig * gg;
            hn = og * tanhf(c_reg);
            h_bits = f2tf(hn);
        }
        g_h[pw_][hidx] = h_bits;         // critical-chain store
        __syncthreads();                 // all h stores done block-wide

        if (tid == 0)
            st_release_gpu(&g_flag[d][myblk * 32], base + 2 + s);

        // out store off the critical chain (nobody reads until pool_kernel)
        if (act)
            out[((size_t)b2 * Tn + t) * (2 * Hn) + d * Hn + j0 + jj] = hn;
    }
}

// ---------------- mean pooling over valid length --------------------------
__global__ void pool_kernel(const int* __restrict__ lengths,
                            float* __restrict__ out) {
    const int c = blockIdx.x * 256 + threadIdx.x;
    const int b = blockIdx.y;
    const float* p = g_out1 + (size_t)b * Tn * (2 * Hn) + c;
    float s = 0.f;
    for (int t = 0; t < Tn; ++t) s += p[(size_t)t * (2 * Hn)];
    out[b * (2 * Hn) + c] = s / (float)lengths[b];
}

// ---------------- launch ---------------------------------------------------
extern "C" void kernel_launch(void* const* d_in, const int* in_sizes, int n_in,
                              void* d_out, int out_size) {
    const float* feats = (const float*)d_in[0];
    const int*   lens  = (const int*)  d_in[1];
    const float* encW  = (const float*)d_in[2];
    const float* encb  = (const float*)d_in[3];
    const float* wih0  = (const float*)d_in[4];
    const float* whh0  = (const float*)d_in[5];
    const float* b0    = (const float*)d_in[6];
    const float* wih1  = (const float*)d_in[7];
    const float* whh1  = (const float*)d_in[8];
    const float* b1    = (const float*)d_in[9];
    float* out = (float*)d_out;

    // opt-in to >48KB dynamic smem (attribute set, not an allocation)
    cudaFuncSetAttribute(proj_gemm,
                         cudaFuncAttributeMaxDynamicSharedMemorySize, PROJ_SMEM);

    zero_kernel<<<2048, 256>>>();
    enc_kernel<<<Bsz * Tn, 256>>>(feats, encW, encb);

    // layer 0: project (K=256) then scan
    {
        dim3 grid(16, 128, 2);
        proj_gemm<<<grid, 256, PROJ_SMEM>>>(0, DENC, wih0, b0);
        rec_kernel<<<NB, 256, REC_SMEM>>>(whh0, lens, 0);
    }
    // layer 1: project (K=1024) then scan
    {
        dim3 grid(16, 128, 2);
        proj_gemm<<<grid, 256, PROJ_SMEM>>>(1, 2 * Hn, wih1, b1);
        rec_kernel<<<NB, 256, REC_SMEM>>>(whh1, lens, 1);
    }

    dim3 pg(4, Bsz);
    pool_kernel<<<pg, 256>>>(lens, out);
}

// round 16
// speedup vs baseline: 1.3277x; 1.3277x over previous
#include <cuda_runtime.h>
#include <math.h>

// Problem constants
#define Bsz   32
#define Tn    512
#define Jn    25
#define DENC  256
#define Hn    512
#define G4    2048      // 4*H
#define NB    128       // persistent recurrence grid (co-resident)
#define NB2   64        // blocks per direction

// ---------------- scratch (device globals; no allocations) ----------------
__device__ float    g_enc [Bsz * Tn * DENC];
__device__ float    g_xg  [2L * Tn * Bsz * G4];           // [d][t][b][4H]
__device__ float    g_out0[Bsz * Tn * 2 * Hn];            // [b][t][2H]
__device__ float    g_out1[Bsz * Tn * 2 * Hn];
__device__ __align__(16) unsigned g_h[2][2 * Bsz * Hn];   // tf32 bits, double-buffered
__device__ unsigned g_flag[2][NB2 * 32];                  // per-block flags, 128B apart

// ---------------- helpers --------------------------------------------------
__device__ __forceinline__ unsigned f2tf(float x) {
    unsigned u;
    asm("cvt.rna.tf32.f32 %0, %1;" : "=r"(u) : "f"(x));
    return u;
}

__device__ __forceinline__ void mma_tf32(float* c,
                                         unsigned a0, unsigned a1,
                                         unsigned a2, unsigned a3,
                                         unsigned b0, unsigned b1) {
    asm("mma.sync.aligned.m16n8k8.row.col.f32.tf32.tf32.f32 "
        "{%0,%1,%2,%3}, {%4,%5,%6,%7}, {%8,%9}, {%0,%1,%2,%3};"
        : "+f"(c[0]), "+f"(c[1]), "+f"(c[2]), "+f"(c[3])
        : "r"(a0), "r"(a1), "r"(a2), "r"(a3), "r"(b0), "r"(b1));
}

__device__ __forceinline__ void st_release_gpu(unsigned* p, unsigned v) {
    asm volatile("st.release.gpu.global.u32 [%0], %1;" :: "l"(p), "r"(v) : "memory");
}
__device__ __forceinline__ unsigned ld_acquire_gpu(const unsigned* p) {
    unsigned v;
    asm volatile("ld.acquire.gpu.global.u32 %0, [%1];" : "=r"(v) : "l"(p) : "memory");
    return v;
}
__device__ __forceinline__ void cp_async16(unsigned smem_addr_bytes,
                                           const void* gptr) {
    asm volatile("cp.async.cg.shared.global [%0], [%1], 16;"
                 :: "r"(smem_addr_bytes), "l"(gptr));
}

// ---------------- zero the output buffers ---------------------------------
__global__ void zero_kernel() {
    const int n4 = (Bsz * Tn * 2 * Hn) / 4;
    float4 z = make_float4(0.f, 0.f, 0.f, 0.f);
    for (int i = blockIdx.x * blockDim.x + threadIdx.x; i < n4;
         i += gridDim.x * blockDim.x) {
        reinterpret_cast<float4*>(g_out0)[i] = z;
        reinterpret_cast<float4*>(g_out1)[i] = z;
    }
}

// ---------------- encoder: relu(masked_xy @ W^T + b) ----------------------
__global__ void enc_kernel(const float* __restrict__ feats,
                           const float* __restrict__ W,
                           const float* __restrict__ bias) {
    __shared__ float xs[2 * Jn];
    const int bt  = blockIdx.x;
    const int tid = threadIdx.x;
    const float* f = feats + (size_t)bt * (Jn * 3);
    if (tid < Jn) {
        float c = (f[tid * 3 + 2] > 0.1f) ? 1.f : 0.f;
        xs[tid * 2 + 0] = f[tid * 3 + 0] * c;
        xs[tid * 2 + 1] = f[tid * 3 + 1] * c;
    }
    __syncthreads();
    const float* w = W + tid * (2 * Jn);
    float s = bias[tid];
#pragma unroll
    for (int k = 0; k < 2 * Jn; ++k) s += xs[k] * w[k];
    g_enc[(size_t)bt * DENC + tid] = fmaxf(s, 0.f);
}

// ---------------- input projection GEMM (tf32, k-tile 32 ping-pong) -------
// out_xg[d][t][b][g] = A[m=b*T+t,:K] . W[d][g,:K] + bias[d][g]
// block 128x128, 8 warps (2m x 4n), k-tile 32, 1 sync per tile
#define PROJ_SMEM (4 * 128 * 36 * 4)
extern __shared__ unsigned smp[];

__global__ void __launch_bounds__(256)
proj_gemm(int srcSel, int K, const float* __restrict__ W,
          const float* __restrict__ bias) {
    const float* A  = srcSel ? g_out0 : g_enc;
    const int d  = blockIdx.z;
    const float* Wd = W + (size_t)d * G4 * K;
    const float* bd = bias + d * G4;
    const int n0 = blockIdx.x * 128;
    const int m0 = blockIdx.y * 128;

    unsigned* As = smp;                   // [2][128*36]
    unsigned* Bs = smp + 2 * 128 * 36;

    const int tid  = threadIdx.x;
    const int lane = tid & 31;
    const int wid  = tid >> 5;
    const int wm   = (wid >> 2) * 64;
    const int wn   = (wid & 3) * 32;

    float acc[4][4][4];
#pragma unroll
    for (int mt = 0; mt < 4; ++mt)
#pragma unroll
        for (int nt = 0; nt < 4; ++nt)
#pragma unroll
            for (int i = 0; i < 4; ++i) acc[mt][nt][i] = 0.f;

    float4 ra[4], rw[4];
#pragma unroll
    for (int j = 0; j < 4; ++j) {
        int u = tid + j * 256, r = u >> 3, kq = (u & 7) << 2;
        ra[j] = *reinterpret_cast<const float4*>(A  + (size_t)(m0 + r) * K + kq);
        rw[j] = *reinterpret_cast<const float4*>(Wd + (size_t)(n0 + r) * K + kq);
    }

    const int KT = K >> 5;
    for (int kt = 0; kt < KT; ++kt) {
        const int p = kt & 1;
#pragma unroll
        for (int j = 0; j < 4; ++j) {
            int u = tid + j * 256, r = u >> 3, kq = (u & 7) << 2;
            uint4 ua, uw;
            ua.x = f2tf(ra[j].x); ua.y = f2tf(ra[j].y);
            ua.z = f2tf(ra[j].z); ua.w = f2tf(ra[j].w);
            uw.x = f2tf(rw[j].x); uw.y = f2tf(rw[j].y);
            uw.z = f2tf(rw[j].z); uw.w = f2tf(rw[j].w);
            *reinterpret_cast<uint4*>(As + p * 4608 + r * 36 + kq) = ua;
            *reinterpret_cast<uint4*>(Bs + p * 4608 + r * 36 + kq) = uw;
        }
        __syncthreads();     // single barrier per k-tile (ping-pong)

        if (kt + 1 < KT) {   // prefetch next tile while computing
            int kb = (kt + 1) * 32;
#pragma unroll
            for (int j = 0; j < 4; ++j) {
                int u = tid + j * 256, r = u >> 3, kq = (u & 7) << 2;
                ra[j] = *reinterpret_cast<const float4*>(A  + (size_t)(m0 + r) * K + kb + kq);
                rw[j] = *reinterpret_cast<const float4*>(Wd + (size_t)(n0 + r) * K + kb + kq);
            }
        }

        const unsigned* Ab = As + p * 4608;
        const unsigned* Bb = Bs + p * 4608;
#pragma unroll
        for (int kk = 0; kk < 32; kk += 8) {
            unsigned af[4][4], bf[4][2];
#pragma unroll
            for (int mt = 0; mt < 4; ++mt) {
                const unsigned* pp = Ab + (wm + mt * 16 + (lane >> 2)) * 36 + kk + (lane & 3);
                af[mt][0] = pp[0];
                af[mt][1] = pp[8 * 36];
                af[mt][2] = pp[4];
                af[mt][3] = pp[8 * 36 + 4];
            }
#pragma unroll
            for (int nt = 0; nt < 4; ++nt) {
                const unsigned* pp = Bb + (wn + nt * 8 + (lane >> 2)) * 36 + kk + (lane & 3);
                bf[nt][0] = pp[0];
                bf[nt][1] = pp[4];
            }
#pragma unroll
            for (int mt = 0; mt < 4; ++mt)
#pragma unroll
                for (int nt = 0; nt < 4; ++nt)
                    mma_tf32(acc[mt][nt], af[mt][0], af[mt][1], af[mt][2], af[mt][3],
                             bf[nt][0], bf[nt][1]);
        }
        __syncthreads();
    }

    // epilogue: bias + scatter to g_xg
#pragma unroll
    for (int mt = 0; mt < 4; ++mt) {
        int mrow0 = m0 + wm + mt * 16 + (lane >> 2);
#pragma unroll
        for (int nt = 0; nt < 4; ++nt) {
            int n = n0 + wn + nt * 8 + (lane & 3) * 2;
            float bv0 = bd[n], bv1 = bd[n + 1];
#pragma unroll
            for (int h = 0; h < 2; ++h) {
                int m  = mrow0 + h * 8;
                int t  = m & (Tn - 1);
                int bb = m >> 9;
                float* cp = g_xg + (((size_t)d * Tn + t) * Bsz + bb) * G4 + n;
                *reinterpret_cast<float2*>(cp) =
                    make_float2(acc[mt][nt][h * 2 + 0] + bv0,
                                acc[mt][nt][h * 2 + 1] + bv1);
            }
        }
    }
}

// ---------------- persistent bidirectional LSTM recurrence (tf32 MMA) -----
// R13 exactly (best-known rec: cp.async warp-private staging + producer-
// subset sync), with ONE change: the out STG is deferred until after the
// release store (pool_kernel is the only reader, at end of launch), taking
// its issue cost off the pre-release critical chain.
#define REC_SMEM ((32 * 516 + 32 * 136) * 4)
extern __shared__ unsigned smr[];

__global__ void __launch_bounds__(256, 1)
rec_kernel(const float* __restrict__ whh,      // [2][4H][H]
           const int*   __restrict__ lengths,
           int outSel) {
    unsigned* hs   = smr;                          // [32 b][516] tf32 bits
    float*    part = (float*)(smr + 32 * 516);     // [32 b][136]
    float* out = outSel ? g_out1 : g_out0;
    const float* xg = g_xg;

    const int tid  = threadIdx.x;
    const int lane = tid & 31;
    const int wid  = tid >> 5;
    const int bx   = blockIdx.x;
    const int d    = bx >> 6;
    const int myblk = bx & 63;
    const int j0   = myblk << 3;
    const int mb   = wid & 1;             // batch half
    const int kc   = wid >> 1;            // K chunk (0..3), 128 k each

    // per-launch flag base + max length (uniform across all blocks)
    __shared__ unsigned s_base;
    __shared__ int s_maxlen;
    if (wid == 0) {
        int L = lengths[lane];
#pragma unroll
        for (int off = 16; off > 0; off >>= 1)
            L = max(L, __shfl_xor_sync(0xffffffffu, L, off));
        if (lane == 0) {
            s_maxlen = L;
            s_base = *(volatile unsigned*)&g_flag[d][myblk * 32];
        }
    }

    // stationary W fragments (B side): b0,b1 per (ks, nt=q)
    unsigned wb0[16][4], wb1[16][4];
    {
        const float* wdb = whh + (size_t)d * G4 * Hn;
#pragma unroll
        for (int ks = 0; ks < 16; ++ks)
#pragma unroll
            for (int nt = 0; nt < 4; ++nt) {
                const float* wp = wdb + (size_t)(nt * Hn + j0 + (lane >> 2)) * Hn
                                  + kc * 128 + ks * 8 + (lane & 3);
                wb0[ks][nt] = f2tf(wp[0]);
                wb1[ks][nt] = f2tf(wp[4]);
            }
    }

    // phase-2 identity: jj-major -> coalesced gmem
    const int jj = tid & 7;
    const int b2 = tid >> 3;              // 0..31
    const int len = lengths[b2];
    const int hidx = (d * Bsz + b2) * Hn + j0 + jj;
    float c_reg = 0.f;
    unsigned h_bits = 0u;
    g_h[0][hidx] = 0u;

    __syncthreads();
    const unsigned base = s_base;
    const int smax = s_maxlen;

    // announce h buffer 0 zeroed (consumers poll per-warp in the loop)
    if (tid == 0) st_release_gpu(&g_flag[d][myblk * 32], base + 1);

    // warp-private staging geometry: rows mb*16..+15, cols kc*128..+127
    const unsigned hs_warp_smem = (unsigned)__cvta_generic_to_shared(hs)
                                  + ((mb * 16) * 516 + kc * 128) * 4;
    const int h_warp_goff = (d * Bsz + mb * 16) * Hn + kc * 128;
    // my 16 producer flags: blocks kc*16 .. kc*16+15 of my direction
    unsigned* prod_flag = (lane < 16)
        ? &g_flag[d][(kc * 16 + lane) * 32] : (unsigned*)0;

    for (int s = 0; s < smax; ++s) {
        const int pr = s & 1, pw_ = pr ^ 1;
        const bool act = s < len;
        const int t = d ? (len - 1 - s) : s;

        // prefetch xg (independent of h; 32B-coalesced per (b,q) group)
        float xv0 = 0.f, xv1 = 0.f, xv2 = 0.f, xv3 = 0.f;
        if (act) {
            const float* xr = xg + (((size_t)d * Tn + t) * Bsz + b2) * G4 + j0 + jj;
            xv0 = xr[0];
            xv1 = xr[Hn];
            xv2 = xr[2 * Hn];
            xv3 = xr[3 * Hn];
        }

        // wait for MY 16 producers only, then stage own fragment region
        {
            const unsigned target = base + 1 + s;
            if (lane < 16) {
                while ((int)(ld_acquire_gpu(prod_flag) - target) < 0) { }
            }
            __syncwarp();
            const unsigned* hsrc = g_h[pr] + h_warp_goff;
#pragma unroll
            for (int i = 0; i < 16; ++i)
                cp_async16(hs_warp_smem + (i * 516 + lane * 4) * 4,
                           hsrc + i * Hn + lane * 4);
            asm volatile("cp.async.commit_group;" ::: "memory");
            asm volatile("cp.async.wait_group 0;" ::: "memory");
            __syncwarp();
        }

        float acc[4][4];
#pragma unroll
        for (int nt = 0; nt < 4; ++nt)
#pragma unroll
            for (int i = 0; i < 4; ++i) acc[nt][i] = 0.f;

#pragma unroll
        for (int ks = 0; ks < 16; ++ks) {
            const unsigned* hp = hs + (mb * 16 + (lane >> 2)) * 516
                                 + kc * 128 + ks * 8 + (lane & 3);
            unsigned a0 = hp[0];
            unsigned a2 = hp[4];
            unsigned a1 = hp[8 * 516];
            unsigned a3 = hp[8 * 516 + 4];
#pragma unroll
            for (int nt = 0; nt < 4; ++nt)
                mma_tf32(acc[nt], a0, a1, a2, a3, wb0[ks][nt], wb1[ks][nt]);
        }

        // write K-chunk partials: part[batch][kc*32 + q*8 + jcol]
        {
            const int b_lo = mb * 16 + (lane >> 2);
            const int col  = kc * 32 + ((lane & 3) << 1);
#pragma unroll
            for (int nt = 0; nt < 4; ++nt) {
                float* pp = part + b_lo * 136 + col + nt * 8;
                *reinterpret_cast<float2*>(pp) =
                    make_float2(acc[nt][0], acc[nt][1]);
                *reinterpret_cast<float2*>(pp + 8 * 136) =
                    make_float2(acc[nt][2], acc[nt][3]);
            }
        }
        __syncthreads();                 // partials complete

        // phase 2: reduce 4 K-chunk partials + gates (conflict-free reads)
        float hn = 0.f;
        if (act) {
            const float* pb = part + b2 * 136 + jj;
            float gv[4];
#pragma unroll
            for (int q = 0; q < 4; ++q) {
                float v = (q == 0) ? xv0 : (q == 1) ? xv1 : (q == 2) ? xv2 : xv3;
#pragma unroll
                for (int k2 = 0; k2 < 4; ++k2)
                    v += pb[k2 * 32 + q * 8];
                gv[q] = v;
            }
            float ig = 1.f / (1.f + __expf(-gv[0]));
            float fg = 1.f / (1.f + __expf(-gv[1]));
            float gg = tanhf(gv[2]);
            float og = 1.f / (1.f + __expf(-gv[3]));
            c_reg = fg * c_reg + ig * gg;
            hn = og * tanhf(c_reg);
            h_bits = f2tf(hn);
        }
        g_h[pw_][hidx] = h_bits;         // critical-chain store
        __syncthreads();                 // all h stores done block-wide

        if (tid == 0)
            st_release_gpu(&g_flag[d][myblk * 32], base + 2 + s);

        // out store off the critical chain (only pool_kernel reads it)
        if (act)
            out[((size_t)b2 * Tn + t) * (2 * Hn) + d * Hn + j0 + jj] = hn;
    }
}

// ---------------- mean pooling over valid length --------------------------
__global__ void pool_kernel(const int* __restrict__ lengths,
                            float* __restrict__ out) {
    const int c = blockIdx.x * 256 + threadIdx.x;
    const int b = blockIdx.y;
    const float* p = g_out1 + (size_t)b * Tn * (2 * Hn) + c;
    float s = 0.f;
    for (int t = 0; t < Tn; ++t) s += p[(size_t)t * (2 * Hn)];
    out[b * (2 * Hn) + c] = s / (float)lengths[b];
}

// ---------------- launch ---------------------------------------------------
extern "C" void kernel_launch(void* const* d_in, const int* in_sizes, int n_in,
                              void* d_out, int out_size) {
    const float* feats = (const float*)d_in[0];
    const int*   lens  = (const int*)  d_in[1];
    const float* encW  = (const float*)d_in[2];
    const float* encb  = (const float*)d_in[3];
    const float* wih0  = (const float*)d_in[4];
    const float* whh0  = (const float*)d_in[5];
    const float* b0    = (const float*)d_in[6];
    const float* wih1  = (const float*)d_in[7];
    const float* whh1  = (const float*)d_in[8];
    const float* b1    = (const float*)d_in[9];
    float* out = (float*)d_out;

    // opt-in to >48KB dynamic smem (attribute set, not an allocation)
    cudaFuncSetAttribute(rec_kernel,
                         cudaFuncAttributeMaxDynamicSharedMemorySize, REC_SMEM);
    cudaFuncSetAttribute(proj_gemm,
                         cudaFuncAttributeMaxDynamicSharedMemorySize, PROJ_SMEM);

    zero_kernel<<<2048, 256>>>();
    enc_kernel<<<Bsz * Tn, 256>>>(feats, encW, encb);

    // layer 0: project (K=256) then scan
    {
        dim3 grid(16, 128, 2);
        proj_gemm<<<grid, 256, PROJ_SMEM>>>(0, DENC, wih0, b0);
        rec_kernel<<<NB, 256, REC_SMEM>>>(whh0, lens, 0);
    }
    // layer 1: project (K=1024) then scan
    {
        dim3 grid(16, 128, 2);
        proj_gemm<<<grid, 256, PROJ_SMEM>>>(1, 2 * Hn, wih1, b1);
        rec_kernel<<<NB, 256, REC_SMEM>>>(whh1, lens, 1);
    }

    dim3 pg(4, Bsz);
    pool_kernel<<<pg, 256>>>(lens, out);
}

// round 17
// speedup vs baseline: 1.3305x; 1.0021x over previous
#include <cuda_runtime.h>
#include <math.h>

// Problem constants
#define Bsz   32
#define Tn    512
#define Jn    25
#define DENC  256
#define Hn    512
#define G4    2048      // 4*H
#define NB    128       // persistent recurrence grid (co-resident)
#define NB2   64        // blocks per direction

// ---------------- scratch (device globals; no allocations) ----------------
__device__ float    g_enc [Bsz * Tn * DENC];              // tf32-rounded
__device__ float    g_xg  [2L * Tn * Bsz * G4];           // [d][t][b][4H]
__device__ float    g_out0[Bsz * Tn * 2 * Hn];            // tf32-rounded (proj-L1 input)
__device__ float    g_out1[Bsz * Tn * 2 * Hn];            // full fp32 (pool input)
__device__ float    g_wtf0[2 * G4 * DENC];                // tf32-rounded w_ih_l0
__device__ float    g_wtf1[2 * G4 * 2 * Hn];              // tf32-rounded w_ih_l1
__device__ __align__(16) unsigned g_h[2][2 * Bsz * Hn];   // tf32 bits, double-buffered
__device__ unsigned g_flag[2][NB2 * 32];                  // per-block flags, 128B apart

// ---------------- helpers --------------------------------------------------
__device__ __forceinline__ unsigned f2tf(float x) {
    unsigned u;
    asm("cvt.rna.tf32.f32 %0, %1;" : "=r"(u) : "f"(x));
    return u;
}

__device__ __forceinline__ void mma_tf32(float* c,
                                         unsigned a0, unsigned a1,
                                         unsigned a2, unsigned a3,
                                         unsigned b0, unsigned b1) {
    asm("mma.sync.aligned.m16n8k8.row.col.f32.tf32.tf32.f32 "
        "{%0,%1,%2,%3}, {%4,%5,%6,%7}, {%8,%9}, {%0,%1,%2,%3};"
        : "+f"(c[0]), "+f"(c[1]), "+f"(c[2]), "+f"(c[3])
        : "r"(a0), "r"(a1), "r"(a2), "r"(a3), "r"(b0), "r"(b1));
}

__device__ __forceinline__ void st_release_gpu(unsigned* p, unsigned v) {
    asm volatile("st.release.gpu.global.u32 [%0], %1;" :: "l"(p), "r"(v) : "memory");
}
__device__ __forceinline__ unsigned ld_acquire_gpu(const unsigned* p) {
    unsigned v;
    asm volatile("ld.acquire.gpu.global.u32 %0, [%1];" : "=r"(v) : "l"(p) : "memory");
    return v;
}
__device__ __forceinline__ void cp_async16(unsigned smem_addr_bytes,
                                           const void* gptr) {
    asm volatile("cp.async.cg.shared.global [%0], [%1], 16;"
                 :: "r"(smem_addr_bytes), "l"(gptr));
}

// ---------------- zero the output buffers ---------------------------------
__global__ void zero_kernel() {
    const int n4 = (Bsz * Tn * 2 * Hn) / 4;
    float4 z = make_float4(0.f, 0.f, 0.f, 0.f);
    for (int i = blockIdx.x * blockDim.x + threadIdx.x; i < n4;
         i += gridDim.x * blockDim.x) {
        reinterpret_cast<float4*>(g_out0)[i] = z;
        reinterpret_cast<float4*>(g_out1)[i] = z;
    }
}

// ---------------- one-shot tf32 rounding of the w_ih weights --------------
__global__ void cvt_kernel(const float* __restrict__ src, float* __restrict__ dst,
                           int n4) {
    int i = blockIdx.x * 256 + threadIdx.x;
    if (i < n4) {
        float4 v = reinterpret_cast<const float4*>(src)[i];
        uint4 u;
        u.x = f2tf(v.x); u.y = f2tf(v.y); u.z = f2tf(v.z); u.w = f2tf(v.w);
        reinterpret_cast<uint4*>(dst)[i] = u;
    }
}

// ---------------- encoder: relu(masked_xy @ W^T + b), tf32-rounded out ----
__global__ void enc_kernel(const float* __restrict__ feats,
                           const float* __restrict__ W,
                           const float* __restrict__ bias) {
    __shared__ float xs[2 * Jn];
    const int bt  = blockIdx.x;
    const int tid = threadIdx.x;
    const float* f = feats + (size_t)bt * (Jn * 3);
    if (tid < Jn) {
        float c = (f[tid * 3 + 2] > 0.1f) ? 1.f : 0.f;
        xs[tid * 2 + 0] = f[tid * 3 + 0] * c;
        xs[tid * 2 + 1] = f[tid * 3 + 1] * c;
    }
    __syncthreads();
    const float* w = W + tid * (2 * Jn);
    float s = bias[tid];
#pragma unroll
    for (int k = 0; k < 2 * Jn; ++k) s += xs[k] * w[k];
    g_enc[(size_t)bt * DENC + tid] =
        __uint_as_float(f2tf(fmaxf(s, 0.f)));   // pre-rounded for proj
}

// ---------------- input projection GEMM (tf32, cp.async pipeline) ---------
// Operands (A and W) are ALREADY tf32-rounded floats in gmem -> stage tiles
// directly with cp.async.cg (no cvt, no register round-trip). Depth-2
// pipeline, ONE __syncthreads per k-tile of 32.
#define PROJ_SMEM (4 * 128 * 36 * 4)
extern __shared__ unsigned smp[];

__global__ void __launch_bounds__(256)
proj_gemm(int srcSel, int K, const float* __restrict__ Wt,
          const float* __restrict__ bias) {
    const float* A  = srcSel ? g_out0 : g_enc;
    const int d  = blockIdx.z;
    const float* Wd = Wt + (size_t)d * G4 * K;
    const float* bd = bias + d * G4;
    const int n0 = blockIdx.x * 128;
    const int m0 = blockIdx.y * 128;

    unsigned* As = smp;                   // [2][128*36]
    unsigned* Bs = smp + 2 * 4608;
    const unsigned As_b = (unsigned)__cvta_generic_to_shared(As);
    const unsigned Bs_b = (unsigned)__cvta_generic_to_shared(Bs);

    const int tid  = threadIdx.x;
    const int lane = tid & 31;
    const int wid  = tid >> 5;
    const int wm   = (wid >> 2) * 64;
    const int wn   = (wid & 3) * 32;

    // per-thread staging coordinates (4 rows of A + 4 rows of W per thread)
    int rj[4], kqj[4];
#pragma unroll
    for (int j = 0; j < 4; ++j) {
        int u = tid + j * 256;
        rj[j]  = u >> 3;
        kqj[j] = (u & 7) << 2;
    }

    float acc[4][4][4];
#pragma unroll
    for (int mt = 0; mt < 4; ++mt)
#pragma unroll
        for (int nt = 0; nt < 4; ++nt)
#pragma unroll
            for (int i = 0; i < 4; ++i) acc[mt][nt][i] = 0.f;

    const int KT = K >> 5;

    // prologue: issue tile 0
#pragma unroll
    for (int j = 0; j < 4; ++j) {
        cp_async16(As_b + (rj[j] * 36 + kqj[j]) * 4,
                   A  + (size_t)(m0 + rj[j]) * K + kqj[j]);
        cp_async16(Bs_b + (rj[j] * 36 + kqj[j]) * 4,
                   Wd + (size_t)(n0 + rj[j]) * K + kqj[j]);
    }
    asm volatile("cp.async.commit_group;" ::: "memory");

    for (int kt = 0; kt < KT; ++kt) {
        asm volatile("cp.async.wait_group 0;" ::: "memory");
        __syncthreads();     // tile kt visible; mma(kt-1) done in all warps

        if (kt + 1 < KT) {   // issue tile kt+1, overlapped with mma(kt)
            const int p = (kt + 1) & 1;
            const int kb = (kt + 1) * 32;
#pragma unroll
            for (int j = 0; j < 4; ++j) {
                cp_async16(As_b + (p * 4608 + rj[j] * 36 + kqj[j]) * 4,
                           A  + (size_t)(m0 + rj[j]) * K + kb + kqj[j]);
                cp_async16(Bs_b + (p * 4608 + rj[j] * 36 + kqj[j]) * 4,
                           Wd + (size_t)(n0 + rj[j]) * K + kb + kqj[j]);
            }
            asm volatile("cp.async.commit_group;" ::: "memory");
        }

        const unsigned* Ab = As + (kt & 1) * 4608;
        const unsigned* Bb = Bs + (kt & 1) * 4608;
#pragma unroll
        for (int kk = 0; kk < 32; kk += 8) {
            unsigned af[4][4], bf[4][2];
#pragma unroll
            for (int mt = 0; mt < 4; ++mt) {
                const unsigned* pp = Ab + (wm + mt * 16 + (lane >> 2)) * 36 + kk + (lane & 3);
                af[mt][0] = pp[0];
                af[mt][1] = pp[8 * 36];
                af[mt][2] = pp[4];
                af[mt][3] = pp[8 * 36 + 4];
            }
#pragma unroll
            for (int nt = 0; nt < 4; ++nt) {
                const unsigned* pp = Bb + (wn + nt * 8 + (lane >> 2)) * 36 + kk + (lane & 3);
                bf[nt][0] = pp[0];
                bf[nt][1] = pp[4];
            }
#pragma unroll
            for (int mt = 0; mt < 4; ++mt)
#pragma unroll
                for (int nt = 0; nt < 4; ++nt)
                    mma_tf32(acc[mt][nt], af[mt][0], af[mt][1], af[mt][2], af[mt][3],
                             bf[nt][0], bf[nt][1]);
        }
    }

    // epilogue: bias + scatter to g_xg
#pragma unroll
    for (int mt = 0; mt < 4; ++mt) {
        int mrow0 = m0 + wm + mt * 16 + (lane >> 2);
#pragma unroll
        for (int nt = 0; nt < 4; ++nt) {
            int n = n0 + wn + nt * 8 + (lane & 3) * 2;
            float bv0 = bd[n], bv1 = bd[n + 1];
#pragma unroll
            for (int h = 0; h < 2; ++h) {
                int m  = mrow0 + h * 8;
                int t  = m & (Tn - 1);
                int bb = m >> 9;
                float* cp = g_xg + (((size_t)d * Tn + t) * Bsz + bb) * G4 + n;
                *reinterpret_cast<float2*>(cp) =
                    make_float2(acc[mt][nt][h * 2 + 0] + bv0,
                                acc[mt][nt][h * 2 + 1] + bv1);
            }
        }
    }
}

// ---------------- persistent bidirectional LSTM recurrence (tf32 MMA) -----
// R15 rec (best known). out0 is stored tf32-rounded (proj-L1 input only);
// out1 stays full fp32 (pool input -> final output bits unchanged).
#define REC_SMEM ((32 * 516 + 32 * 136) * 4)
extern __shared__ unsigned smr[];

__global__ void __launch_bounds__(256, 1)
rec_kernel(const float* __restrict__ whh,      // [2][4H][H]
           const int*   __restrict__ lengths,
           int outSel) {
    unsigned* hs   = smr;                          // [32 b][516] tf32 bits
    float*    part = (float*)(smr + 32 * 516);     // [32 b][136]
    float* out = outSel ? g_out1 : g_out0;
    const float* xg = g_xg;

    const int tid  = threadIdx.x;
    const int lane = tid & 31;
    const int wid  = tid >> 5;
    const int bx   = blockIdx.x;
    const int d    = bx >> 6;
    const int myblk = bx & 63;
    const int j0   = myblk << 3;
    const int mb   = wid & 1;             // batch half
    const int kc   = wid >> 1;            // K chunk (0..3), 128 k each

    // per-launch flag base + max length (uniform across all blocks)
    __shared__ unsigned s_base;
    __shared__ int s_maxlen;
    if (wid == 0) {
        int L = lengths[lane];
#pragma unroll
        for (int off = 16; off > 0; off >>= 1)
            L = max(L, __shfl_xor_sync(0xffffffffu, L, off));
        if (lane == 0) {
            s_maxlen = L;
            s_base = *(volatile unsigned*)&g_flag[d][myblk * 32];
        }
    }

    // stationary W fragments (B side): b0,b1 per (ks, nt=q)
    unsigned wb0[16][4], wb1[16][4];
    {
        const float* wdb = whh + (size_t)d * G4 * Hn;
#pragma unroll
        for (int ks = 0; ks < 16; ++ks)
#pragma unroll
            for (int nt = 0; nt < 4; ++nt) {
                const float* wp = wdb + (size_t)(nt * Hn + j0 + (lane >> 2)) * Hn
                                  + kc * 128 + ks * 8 + (lane & 3);
                wb0[ks][nt] = f2tf(wp[0]);
                wb1[ks][nt] = f2tf(wp[4]);
            }
    }

    // phase-2 identity: jj-major -> coalesced gmem
    const int jj = tid & 7;
    const int b2 = tid >> 3;              // 0..31
    const int len = lengths[b2];
    const int hidx = (d * Bsz + b2) * Hn + j0 + jj;
    float c_reg = 0.f;
    unsigned h_bits = 0u;
    g_h[0][hidx] = 0u;

    __syncthreads();
    const unsigned base = s_base;
    const int smax = s_maxlen;

    // announce h buffer 0 zeroed (consumers poll per-warp in the loop)
    if (tid == 0) st_release_gpu(&g_flag[d][myblk * 32], base + 1);

    // warp-private staging geometry: rows mb*16..+15, cols kc*128..+127
    const unsigned hs_warp_smem = (unsigned)__cvta_generic_to_shared(hs)
                                  + ((mb * 16) * 516 + kc * 128) * 4;
    const int h_warp_goff = (d * Bsz + mb * 16) * Hn + kc * 128;
    // my 16 producer flags: blocks kc*16 .. kc*16+15 of my direction
    unsigned* prod_flag = (lane < 16)
        ? &g_flag[d][(kc * 16 + lane) * 32] : (unsigned*)0;

    for (int s = 0; s < smax; ++s) {
        const int pr = s & 1, pw_ = pr ^ 1;
        const bool act = s < len;
        const int t = d ? (len - 1 - s) : s;

        // prefetch xg (independent of h; 32B-coalesced per (b,q) group)
        float xv0 = 0.f, xv1 = 0.f, xv2 = 0.f, xv3 = 0.f;
        if (act) {
            const float* xr = xg + (((size_t)d * Tn + t) * Bsz + b2) * G4 + j0 + jj;
            xv0 = xr[0];
            xv1 = xr[Hn];
            xv2 = xr[2 * Hn];
            xv3 = xr[3 * Hn];
        }

        // wait for MY 16 producers only, then stage own fragment region
        {
            const unsigned target = base + 1 + s;
            if (lane < 16) {
                while ((int)(ld_acquire_gpu(prod_flag) - target) < 0) { }
            }
            __syncwarp();
            const unsigned* hsrc = g_h[pr] + h_warp_goff;
#pragma unroll
            for (int i = 0; i < 16; ++i)
                cp_async16(hs_warp_smem + (i * 516 + lane * 4) * 4,
                           hsrc + i * Hn + lane * 4);
            asm volatile("cp.async.commit_group;" ::: "memory");
            asm volatile("cp.async.wait_group 0;" ::: "memory");
            __syncwarp();
        }

        float acc[4][4];
#pragma unroll
        for (int nt = 0; nt < 4; ++nt)
#pragma unroll
            for (int i = 0; i < 4; ++i) acc[nt][i] = 0.f;

#pragma unroll
        for (int ks = 0; ks < 16; ++ks) {
            const unsigned* hp = hs + (mb * 16 + (lane >> 2)) * 516
                                 + kc * 128 + ks * 8 + (lane & 3);
            unsigned a0 = hp[0];
            unsigned a2 = hp[4];
            unsigned a1 = hp[8 * 516];
            unsigned a3 = hp[8 * 516 + 4];
#pragma unroll
            for (int nt = 0; nt < 4; ++nt)
                mma_tf32(acc[nt], a0, a1, a2, a3, wb0[ks][nt], wb1[ks][nt]);
        }

        // write K-chunk partials: part[batch][kc*32 + q*8 + jcol]
        {
            const int b_lo = mb * 16 + (lane >> 2);
            const int col  = kc * 32 + ((lane & 3) << 1);
#pragma unroll
            for (int nt = 0; nt < 4; ++nt) {
                float* pp = part + b_lo * 136 + col + nt * 8;
                *reinterpret_cast<float2*>(pp) =
                    make_float2(acc[nt][0], acc[nt][1]);
                *reinterpret_cast<float2*>(pp + 8 * 136) =
                    make_float2(acc[nt][2], acc[nt][3]);
            }
        }
        __syncthreads();                 // partials complete

        // phase 2: reduce 4 K-chunk partials + gates (conflict-free reads)
        float hn = 0.f;
        if (act) {
            const float* pb = part + b2 * 136 + jj;
            float gv[4];
#pragma unroll
            for (int q = 0; q < 4; ++q) {
                float v = (q == 0) ? xv0 : (q == 1) ? xv1 : (q == 2) ? xv2 : xv3;
#pragma unroll
                for (int k2 = 0; k2 < 4; ++k2)
                    v += pb[k2 * 32 + q * 8];
                gv[q] = v;
            }
            float ig = 1.f / (1.f + __expf(-gv[0]));
            float fg = 1.f / (1.f + __expf(-gv[1]));
            float gg = tanhf(gv[2]);
            float og = 1.f / (1.f + __expf(-gv[3]));
            c_reg = fg * c_reg + ig * gg;
            hn = og * tanhf(c_reg);
            h_bits = f2tf(hn);
        }
        g_h[pw_][hidx] = h_bits;         // critical-chain store
        __syncthreads();                 // all h stores done block-wide

        if (tid == 0)
            st_release_gpu(&g_flag[d][myblk * 32], base + 2 + s);

        // out store off the critical chain (only proj-L1/pool read it).
        // layer-0 output pre-rounded to tf32 (== what proj would compute).
        if (act)
            out[((size_t)b2 * Tn + t) * (2 * Hn) + d * Hn + j0 + jj] =
                outSel ? hn : __uint_as_float(h_bits);
    }
}

// ---------------- mean pooling over valid length --------------------------
__global__ void pool_kernel(const int* __restrict__ lengths,
                            float* __restrict__ out) {
    const int c = blockIdx.x * 256 + threadIdx.x;
    const int b = blockIdx.y;
    const float* p = g_out1 + (size_t)b * Tn * (2 * Hn) + c;
    float s = 0.f;
    for (int t = 0; t < Tn; ++t) s += p[(size_t)t * (2 * Hn)];
    out[b * (2 * Hn) + c] = s / (float)lengths[b];
}

// ---------------- launch ---------------------------------------------------
extern "C" void kernel_launch(void* const* d_in, const int* in_sizes, int n_in,
                              void* d_out, int out_size) {
    const float* feats = (const float*)d_in[0];
    const int*   lens  = (const int*)  d_in[1];
    const float* encW  = (const float*)d_in[2];
    const float* encb  = (const float*)d_in[3];
    const float* wih0  = (const float*)d_in[4];
    const float* whh0  = (const float*)d_in[5];
    const float* b0    = (const float*)d_in[6];
    const float* wih1  = (const float*)d_in[7];
    const float* whh1  = (const float*)d_in[8];
    const float* b1    = (const float*)d_in[9];
    float* out = (float*)d_out;

    // opt-in to >48KB dynamic smem (attribute set, not an allocation)
    cudaFuncSetAttribute(rec_kernel,
                         cudaFuncAttributeMaxDynamicSharedMemorySize, REC_SMEM);
    cudaFuncSetAttribute(proj_gemm,
                         cudaFuncAttributeMaxDynamicSharedMemorySize, PROJ_SMEM);

    zero_kernel<<<2048, 256>>>();
    // pre-round the input-projection weights to tf32 (one-shot)
    {
        float* w0;  cudaGetSymbolAddress((void**)&w0, g_wtf0);
        float* w1;  cudaGetSymbolAddress((void**)&w1, g_wtf1);
        cvt_kernel<<<(2 * G4 * DENC / 4 + 255) / 256, 256>>>(wih0, w0,
                                                             2 * G4 * DENC / 4);
        cvt_kernel<<<(2 * G4 * 2 * Hn / 4 + 255) / 256, 256>>>(wih1, w1,
                                                               2 * G4 * 2 * Hn / 4);
    }
    enc_kernel<<<Bsz * Tn, 256>>>(feats, encW, encb);

    float* w0;  cudaGetSymbolAddress((void**)&w0, g_wtf0);
    float* w1;  cudaGetSymbolAddress((void**)&w1, g_wtf1);

    // layer 0: project (K=256) then scan
    {
        dim3 grid(16, 128, 2);
        proj_gemm<<<grid, 256, PROJ_SMEM>>>(0, DENC, w0, b0);
        rec_kernel<<<NB, 256, REC_SMEM>>>(whh0, lens, 0);
    }
    // layer 1: project (K=1024) then scan
    {
        dim3 grid(16, 128, 2);
        proj_gemm<<<grid, 256, PROJ_SMEM>>>(1, 2 * Hn, w1, b1);
        rec_kernel<<<NB, 256, REC_SMEM>>>(whh1, lens, 1);
    }

    dim3 pg(4, Bsz);
    pool_kernel<<<pg, 256>>>(lens, out);
}